// round 1
// baseline (speedup 1.0000x reference)
#include <cuda_runtime.h>

// Problem constants
#define BATCH   4
#define NQ      1024
#define NCTX    1024
#define NJ      2048      // NQ + NCTX
#define DMODEL  768
#define HEADS   12
#define DHEAD   64
#define INNER   768       // HEADS*DHEAD
#define SCALE   0.125f    // 64^-0.5

// ---------------------------------------------------------------------------
// Scratch (device globals; no allocation allowed in kernel_launch)
// ---------------------------------------------------------------------------
__device__ float g_q  [BATCH * NQ * INNER];                 // [b, i, h*64+d]   12.6 MB
__device__ float g_kv [BATCH * NJ * 2 * INNER];             // [b, j, 1536] (k|v) 50 MB
__device__ float g_dots[(size_t)BATCH * NQ * HEADS * NJ];   // [b, i, h, j]     402 MB
__device__ float g_ao [BATCH * NQ * INNER];                 // attention output 12.6 MB

// ---------------------------------------------------------------------------
// Generic fp32 SGEMM: C = alpha * A x B (+bias), batched via 2-level z index.
//   A: [M,K] row-major, optionally gathered (concat of A / A2 along rows)
//   B: BT=false -> [K,N] row-major;  BT=true -> [N,K] row-major (NT gemm)
// ---------------------------------------------------------------------------
struct GemmParams {
    const float* A;
    const float* A2;       // second source for GATHER mode
    const float* B;
    float*       C;
    const float* bias;     // nullable
    int M, N, K;
    int lda, ldb, ldc;
    int Z2;                // z = z1*Z2 + z2
    long as1, as2, bs1, bs2, cs1, cs2;
    float alpha;
    int gatherSplit;       // rows < split from A, else from A2
};

template<int BM, int BN, int BK, int TM, int TN, bool BT, bool GATHER>
__global__ void __launch_bounds__(256) gemm_kernel(GemmParams p) {
    __shared__ float As[BK][BM + 4];
    __shared__ float Bs[BK][BN + 4];

    const int z  = blockIdx.z;
    const int z1 = z / p.Z2;
    const int z2 = z - z1 * p.Z2;
    const float* A  = p.A + z1 * p.as1 + z2 * p.as2;
    const float* A2 = GATHER ? (p.A2 + z1 * p.as1) : nullptr;
    const float* B  = p.B + z1 * p.bs1 + z2 * p.bs2;
    float*       C  = p.C + z1 * p.cs1 + z2 * p.cs2;

    const int m0 = blockIdx.y * BM;
    const int n0 = blockIdx.x * BN;
    const int tid = threadIdx.x;

    const int tx = tid % (BN / TN);
    const int ty = tid / (BN / TN);

    float acc[TM][TN];
#pragma unroll
    for (int i = 0; i < TM; i++)
#pragma unroll
        for (int j = 0; j < TN; j++) acc[i][j] = 0.0f;

    for (int k0 = 0; k0 < p.K; k0 += BK) {
        // ---- load A tile (BM x BK), store transposed ----
#pragma unroll
        for (int t = tid; t < BM * BK / 4; t += 256) {
            int row = t / (BK / 4);
            int c4  = (t % (BK / 4)) * 4;
            const float* ap;
            if (GATHER) {
                int m = m0 + row;
                ap = (m < p.gatherSplit)
                         ? (A  + (long)m * p.lda)
                         : (A2 + (long)(m - p.gatherSplit) * p.lda);
            } else {
                ap = A + (long)(m0 + row) * p.lda;
            }
            float4 v = *(const float4*)(ap + k0 + c4);
            As[c4 + 0][row] = v.x;
            As[c4 + 1][row] = v.y;
            As[c4 + 2][row] = v.z;
            As[c4 + 3][row] = v.w;
        }
        // ---- load B tile ----
        if (BT) {
            // B rows are N (K-contiguous): transpose into Bs[k][n]
#pragma unroll
            for (int t = tid; t < BN * BK / 4; t += 256) {
                int row = t / (BK / 4);
                int c4  = (t % (BK / 4)) * 4;
                float4 v = *(const float4*)(B + (long)(n0 + row) * p.ldb + k0 + c4);
                Bs[c4 + 0][row] = v.x;
                Bs[c4 + 1][row] = v.y;
                Bs[c4 + 2][row] = v.z;
                Bs[c4 + 3][row] = v.w;
            }
        } else {
#pragma unroll
            for (int t = tid; t < BK * BN / 4; t += 256) {
                int row = t / (BN / 4);
                int c4  = (t % (BN / 4)) * 4;
                float4 v = *(const float4*)(B + (long)(k0 + row) * p.ldb + n0 + c4);
                *(float4*)&Bs[row][c4] = v;
            }
        }
        __syncthreads();

#pragma unroll
        for (int k = 0; k < BK; k++) {
            float a[TM], b[TN];
#pragma unroll
            for (int i = 0; i < TM; i += 4) {
                float4 v = *(const float4*)&As[k][ty * TM + i];
                a[i] = v.x; a[i + 1] = v.y; a[i + 2] = v.z; a[i + 3] = v.w;
            }
#pragma unroll
            for (int j = 0; j < TN; j += 4) {
                float4 v = *(const float4*)&Bs[k][tx * TN + j];
                b[j] = v.x; b[j + 1] = v.y; b[j + 2] = v.z; b[j + 3] = v.w;
            }
#pragma unroll
            for (int i = 0; i < TM; i++)
#pragma unroll
                for (int j = 0; j < TN; j++)
                    acc[i][j] += a[i] * b[j];
        }
        __syncthreads();
    }

    // ---- epilogue ----
#pragma unroll
    for (int i = 0; i < TM; i++) {
        long crow = (long)(m0 + ty * TM + i) * p.ldc + n0 + tx * TN;
#pragma unroll
        for (int j = 0; j < TN; j += 4) {
            float4 v;
            v.x = acc[i][j + 0] * p.alpha;
            v.y = acc[i][j + 1] * p.alpha;
            v.z = acc[i][j + 2] * p.alpha;
            v.w = acc[i][j + 3] * p.alpha;
            if (p.bias) {
                int c = n0 + tx * TN + j;
                v.x += p.bias[c + 0];
                v.y += p.bias[c + 1];
                v.z += p.bias[c + 2];
                v.w += p.bias[c + 3];
            }
            *(float4*)&C[crow + j] = v;
        }
    }
}

// ---------------------------------------------------------------------------
// Fused talking-heads: pre-mix -> softmax(j) -> post-mix, in-place on g_dots.
// One CTA per (b,i). The 12x2048 slice lives in SMEM (96 KB).
// ---------------------------------------------------------------------------
#define K4_SMEM ((HEADS * NJ + 2 * HEADS * HEADS) * 4)

__global__ void __launch_bounds__(512) mix_softmax_kernel(
    float* __restrict__ dots,
    const float* __restrict__ mp_pre,
    const float* __restrict__ mp_post)
{
    extern __shared__ float sm[];
    float* s    = sm;                       // [12][2048]
    float* pre  = sm + HEADS * NJ;          // [144]
    float* post = pre + HEADS * HEADS;      // [144]

    const int tid = threadIdx.x;
    const long base = (long)blockIdx.x * (HEADS * NJ);

    if (tid < HEADS * HEADS) {
        pre[tid]  = mp_pre[tid];
        post[tid] = mp_post[tid];
    }
    {
        const float4* g4 = (const float4*)(dots + base);
        float4* s4 = (float4*)s;
        for (int t = tid; t < HEADS * NJ / 4; t += 512) s4[t] = g4[t];
    }
    __syncthreads();

    const int j0 = tid * 4;  // each thread owns 4 consecutive j columns

    // ---- pre-softmax mix: mixed[g][j] = sum_h raw[h][j] * pre[h][g] ----
    float4 r[HEADS];
    {
        float4 raw[HEADS];
#pragma unroll
        for (int h = 0; h < HEADS; h++) raw[h] = *(float4*)&s[h * NJ + j0];
#pragma unroll
        for (int g = 0; g < HEADS; g++) {
            float4 a = make_float4(0.f, 0.f, 0.f, 0.f);
#pragma unroll
            for (int h = 0; h < HEADS; h++) {
                float w = pre[h * HEADS + g];
                a.x += raw[h].x * w;
                a.y += raw[h].y * w;
                a.z += raw[h].z * w;
                a.w += raw[h].w * w;
            }
            r[g] = a;
        }
    }
    __syncthreads();
#pragma unroll
    for (int g = 0; g < HEADS; g++) *(float4*)&s[g * NJ + j0] = r[g];
    __syncthreads();

    // ---- softmax over j, one warp per head-row ----
    const int w = tid >> 5, lane = tid & 31;
    if (w < HEADS) {
        float* row = s + w * NJ;
        float m = -1e30f;
        for (int j = lane; j < NJ; j += 32) m = fmaxf(m, row[j]);
#pragma unroll
        for (int o = 16; o; o >>= 1) m = fmaxf(m, __shfl_xor_sync(0xFFFFFFFFu, m, o));
        float zs = 0.f;
        for (int j = lane; j < NJ; j += 32) {
            float e = __expf(row[j] - m);
            row[j] = e;
            zs += e;
        }
#pragma unroll
        for (int o = 16; o; o >>= 1) zs += __shfl_xor_sync(0xFFFFFFFFu, zs, o);
        float inv = 1.0f / zs;
        for (int j = lane; j < NJ; j += 32) row[j] *= inv;
    }
    __syncthreads();

    // ---- post-softmax mix, write back to global ----
    {
        float4 raw[HEADS];
#pragma unroll
        for (int h = 0; h < HEADS; h++) raw[h] = *(float4*)&s[h * NJ + j0];
#pragma unroll
        for (int g = 0; g < HEADS; g++) {
            float4 a = make_float4(0.f, 0.f, 0.f, 0.f);
#pragma unroll
            for (int h = 0; h < HEADS; h++) {
                float w = post[h * HEADS + g];
                a.x += raw[h].x * w;
                a.y += raw[h].y * w;
                a.z += raw[h].z * w;
                a.w += raw[h].w * w;
            }
            *(float4*)&dots[base + g * NJ + j0] = a;
        }
    }
}

// ---------------------------------------------------------------------------
// Launch: 6-stage pipeline
// ---------------------------------------------------------------------------
extern "C" void kernel_launch(void* const* d_in, const int* in_sizes, int n_in,
                              void* d_out, int out_size) {
    (void)in_sizes; (void)n_in; (void)out_size;
    const float* x       = (const float*)d_in[0];
    const float* context = (const float*)d_in[1];
    const float* Wq      = (const float*)d_in[2];
    const float* Wkv     = (const float*)d_in[3];
    const float* mix_pre = (const float*)d_in[4];
    const float* mix_post= (const float*)d_in[5];
    const float* Wout    = (const float*)d_in[6];
    const float* b_out   = (const float*)d_in[7];
    float* out = (float*)d_out;

    float *q, *kv, *dots, *ao;
    cudaGetSymbolAddress((void**)&q,    g_q);
    cudaGetSymbolAddress((void**)&kv,   g_kv);
    cudaGetSymbolAddress((void**)&dots, g_dots);
    cudaGetSymbolAddress((void**)&ao,   g_ao);

    const long Q_B  = (long)NQ * INNER;        //  786432  (q batch stride)
    const long KV_B = (long)NJ * 2 * INNER;    // 3145728  (kv batch stride)
    const long D_B  = (long)NQ * HEADS * NJ;   // 25165824 (dots batch stride)

    // K1: q = x @ Wq    [4096,768] = [4096,768]@[768,768]
    {
        GemmParams p = {};
        p.A = x; p.B = Wq; p.C = q;
        p.M = BATCH * NQ; p.N = INNER; p.K = DMODEL;
        p.lda = DMODEL; p.ldb = INNER; p.ldc = INNER;
        p.Z2 = 1; p.alpha = 1.0f;
        gemm_kernel<128,128,8,8,8,false,false><<<dim3(INNER/128, BATCH*NQ/128, 1), 256>>>(p);
    }
    // K2: kv = concat(x, context) @ Wkv   per-batch [2048,1536]
    {
        GemmParams p = {};
        p.A = x; p.A2 = context; p.B = Wkv; p.C = kv;
        p.M = NJ; p.N = 2 * INNER; p.K = DMODEL;
        p.lda = DMODEL; p.ldb = 2 * INNER; p.ldc = 2 * INNER;
        p.Z2 = 1; p.as1 = (long)NQ * DMODEL; p.cs1 = KV_B;
        p.alpha = 1.0f; p.gatherSplit = NQ;
        gemm_kernel<128,128,8,8,8,false,true><<<dim3(2*INNER/128, NJ/128, BATCH), 256>>>(p);
    }
    // K3: dots[b,i,h,j] = SCALE * q_h[i,:] . k_h[j,:]   (NT, 48 batches)
    {
        GemmParams p = {};
        p.A = q; p.B = kv; p.C = dots;
        p.M = NQ; p.N = NJ; p.K = DHEAD;
        p.lda = INNER; p.ldb = 2 * INNER; p.ldc = HEADS * NJ;
        p.Z2 = HEADS;
        p.as1 = Q_B;  p.as2 = DHEAD;
        p.bs1 = KV_B; p.bs2 = DHEAD;
        p.cs1 = D_B;  p.cs2 = NJ;
        p.alpha = SCALE;
        gemm_kernel<128,128,8,8,8,true,false><<<dim3(NJ/128, NQ/128, BATCH*HEADS), 256>>>(p);
    }
    // K4: fused pre-mix -> softmax -> post-mix, in-place
    {
        cudaFuncSetAttribute(mix_softmax_kernel,
                             cudaFuncAttributeMaxDynamicSharedMemorySize, K4_SMEM);
        mix_softmax_kernel<<<BATCH * NQ, 512, K4_SMEM>>>(dots, mix_pre, mix_post);
    }
    // K5: ao[b,i,g*64+d] = attn[b,g,i,:] @ v[b,g,:,d]   (NN, 48 batches)
    {
        GemmParams p = {};
        p.A = dots; p.B = kv + INNER; p.C = ao;
        p.M = NQ; p.N = DHEAD; p.K = NJ;
        p.lda = HEADS * NJ; p.ldb = 2 * INNER; p.ldc = INNER;
        p.Z2 = HEADS;
        p.as1 = D_B;  p.as2 = NJ;
        p.bs1 = KV_B; p.bs2 = DHEAD;
        p.cs1 = Q_B;  p.cs2 = DHEAD;
        p.alpha = 1.0f;
        gemm_kernel<128,64,8,8,4,false,false><<<dim3(1, NQ/128, BATCH*HEADS), 256>>>(p);
    }
    // K6: out = ao @ Wout + b_out
    {
        GemmParams p = {};
        p.A = ao; p.B = Wout; p.C = out; p.bias = b_out;
        p.M = BATCH * NQ; p.N = DMODEL; p.K = INNER;
        p.lda = INNER; p.ldb = DMODEL; p.ldc = DMODEL;
        p.Z2 = 1; p.alpha = 1.0f;
        gemm_kernel<128,128,8,8,8,false,false><<<dim3(DMODEL/128, BATCH*NQ/128, 1), 256>>>(p);
    }
}

// round 2
// speedup vs baseline: 1.0637x; 1.0637x over previous
#include <cuda_runtime.h>

// Problem constants
#define BATCH   4
#define NQ      1024
#define NJ      2048
#define DMODEL  768
#define HEADS   12
#define DHEAD   64
#define INNER   768
#define SCALE   0.125f

// ---------------------------------------------------------------------------
// Scratch
// ---------------------------------------------------------------------------
__device__ float g_q  [BATCH * NQ * INNER];
__device__ float g_kv [BATCH * NJ * 2 * INNER];
__device__ float g_dots[(size_t)BATCH * NQ * HEADS * NJ];
__device__ float g_ao [BATCH * NQ * INNER];

struct GemmParams {
    const float* A;
    const float* A2;
    const float* B;
    float*       C;
    const float* bias;
    int M, N, K;
    int lda, ldb, ldc;
    int Z2;
    long as1, as2, bs1, bs2, cs1, cs2;
    float alpha;
    int gatherSplit;
};

// round-to-nearest tf32 (result is a valid fp32 bit pattern, low 13 mantissa = 0)
__device__ __forceinline__ float f2tf(float x) {
    unsigned u;
    asm("cvt.rna.tf32.f32 %0, %1;" : "=r"(u) : "f"(x));
    return __uint_as_float(u);
}

__device__ __forceinline__ void mma_tf32(float* c, const float* a, float b0, float b1) {
    asm volatile(
        "mma.sync.aligned.m16n8k8.row.col.f32.tf32.tf32.f32 "
        "{%0,%1,%2,%3},{%4,%5,%6,%7},{%8,%9},{%0,%1,%2,%3};"
        : "+f"(c[0]), "+f"(c[1]), "+f"(c[2]), "+f"(c[3])
        : "r"(__float_as_uint(a[0])), "r"(__float_as_uint(a[1])),
          "r"(__float_as_uint(a[2])), "r"(__float_as_uint(a[3])),
          "r"(__float_as_uint(b0)),  "r"(__float_as_uint(b1)));
}

// ---------------------------------------------------------------------------
// 3xTF32 split-precision tensor-core GEMM (fp32-accurate).
//   A: [M,K] row-major (optional 2-source gather over rows)
//   B: BT=false -> [K,N] row-major;  BT=true -> [N,K] row-major
// ---------------------------------------------------------------------------
template<int BM, int BN, int BK, int WM, int WN, bool BT, bool GATHER>
__global__ void __launch_bounds__((BM/WM)*(BN/WN)*32, 2) mma_gemm(GemmParams p) {
    constexpr int WARPS_M = BM / WM;
    constexpr int WARPS_N = BN / WN;
    constexpr int THREADS = WARPS_M * WARPS_N * 32;
    constexpr int MT  = WM / 16;   // m16 tiles per warp
    constexpr int NTL = WN / 8;    // n8 tiles per warp
    constexpr int KS  = BK / 8;    // k8 steps per slab
    constexpr int LDA = BM + 4;
    constexpr int LDB = BN + 4;

    __shared__ float Ahi[BK][LDA], Alo[BK][LDA];
    __shared__ float Bhi[BK][LDB], Blo[BK][LDB];

    const int z  = blockIdx.z;
    const int z1 = z / p.Z2;
    const int z2 = z - z1 * p.Z2;
    const float* A  = p.A + z1 * p.as1 + z2 * p.as2;
    const float* A2 = GATHER ? (p.A2 + z1 * p.as1) : nullptr;
    const float* B  = p.B + z1 * p.bs1 + z2 * p.bs2;
    float*       C  = p.C + z1 * p.cs1 + z2 * p.cs2;

    const int m0 = blockIdx.y * BM;
    const int n0 = blockIdx.x * BN;
    const int tid  = threadIdx.x;
    const int wid  = tid >> 5;
    const int lane = tid & 31;
    const int wm = wid % WARPS_M;
    const int wn = wid / WARPS_M;
    const int g = lane >> 2;       // group id (0..7)
    const int t = lane & 3;        // thread in group

    float acc[MT][NTL][4];
#pragma unroll
    for (int mi = 0; mi < MT; mi++)
#pragma unroll
        for (int ni = 0; ni < NTL; ni++)
#pragma unroll
            for (int e = 0; e < 4; e++) acc[mi][ni][e] = 0.0f;

    for (int k0 = 0; k0 < p.K; k0 += BK) {
        // ---- A tile: BM x BK, split into hi/lo, stored transposed [k][m] ----
#pragma unroll
        for (int it = tid; it < BM * BK / 4; it += THREADS) {
            int row = it / (BK / 4);
            int c4  = (it % (BK / 4)) * 4;
            const float* ap;
            if (GATHER) {
                int m = m0 + row;
                ap = (m < p.gatherSplit)
                         ? (A  + (long)m * p.lda)
                         : (A2 + (long)(m - p.gatherSplit) * p.lda);
            } else {
                ap = A + (long)(m0 + row) * p.lda;
            }
            float4 v = *(const float4*)(ap + k0 + c4);
            float vv[4] = {v.x, v.y, v.z, v.w};
#pragma unroll
            for (int e = 0; e < 4; e++) {
                float hi = f2tf(vv[e]);
                Ahi[c4 + e][row] = hi;
                Alo[c4 + e][row] = f2tf(vv[e] - hi);
            }
        }
        // ---- B tile -> [k][n] hi/lo ----
        if (BT) {
#pragma unroll
            for (int it = tid; it < BN * BK / 4; it += THREADS) {
                int row = it / (BK / 4);       // n index
                int c4  = (it % (BK / 4)) * 4; // k index
                float4 v = *(const float4*)(B + (long)(n0 + row) * p.ldb + k0 + c4);
                float vv[4] = {v.x, v.y, v.z, v.w};
#pragma unroll
                for (int e = 0; e < 4; e++) {
                    float hi = f2tf(vv[e]);
                    Bhi[c4 + e][row] = hi;
                    Blo[c4 + e][row] = f2tf(vv[e] - hi);
                }
            }
        } else {
#pragma unroll
            for (int it = tid; it < BK * BN / 4; it += THREADS) {
                int row = it / (BN / 4);       // k index
                int c4  = (it % (BN / 4)) * 4; // n index
                float4 v = *(const float4*)(B + (long)(k0 + row) * p.ldb + n0 + c4);
                float vv[4] = {v.x, v.y, v.z, v.w};
#pragma unroll
                for (int e = 0; e < 4; e++) {
                    float hi = f2tf(vv[e]);
                    Bhi[row][c4 + e] = hi;
                    Blo[row][c4 + e] = f2tf(vv[e] - hi);
                }
            }
        }
        __syncthreads();

#pragma unroll
        for (int ks = 0; ks < KS; ks++) {
            const int kb = ks * 8;
            // A fragments (hi and lo) for this k-step
            float ahi[MT][4], alo[MT][4];
#pragma unroll
            for (int mi = 0; mi < MT; mi++) {
                int rb = wm * WM + mi * 16;
                ahi[mi][0] = Ahi[kb + t    ][rb + g];
                ahi[mi][1] = Ahi[kb + t    ][rb + g + 8];
                ahi[mi][2] = Ahi[kb + t + 4][rb + g];
                ahi[mi][3] = Ahi[kb + t + 4][rb + g + 8];
                alo[mi][0] = Alo[kb + t    ][rb + g];
                alo[mi][1] = Alo[kb + t    ][rb + g + 8];
                alo[mi][2] = Alo[kb + t + 4][rb + g];
                alo[mi][3] = Alo[kb + t + 4][rb + g + 8];
            }
#pragma unroll
            for (int ni = 0; ni < NTL; ni++) {
                int cb = wn * WN + ni * 8 + g;
                float bh0 = Bhi[kb + t    ][cb];
                float bh1 = Bhi[kb + t + 4][cb];
                float bl0 = Blo[kb + t    ][cb];
                float bl1 = Blo[kb + t + 4][cb];
#pragma unroll
                for (int mi = 0; mi < MT; mi++) {
                    mma_tf32(acc[mi][ni], ahi[mi], bh0, bh1);  // hi*hi
                    mma_tf32(acc[mi][ni], ahi[mi], bl0, bl1);  // hi*lo
                    mma_tf32(acc[mi][ni], alo[mi], bh0, bh1);  // lo*hi
                }
            }
        }
        __syncthreads();
    }

    // ---- epilogue ----
#pragma unroll
    for (int mi = 0; mi < MT; mi++) {
        int r0 = m0 + wm * WM + mi * 16 + g;
#pragma unroll
        for (int ni = 0; ni < NTL; ni++) {
            int col = n0 + wn * WN + ni * 8 + t * 2;
            float bx = 0.f, by = 0.f;
            if (p.bias) { bx = p.bias[col]; by = p.bias[col + 1]; }
            float2 v0, v1;
            v0.x = acc[mi][ni][0] * p.alpha + bx;
            v0.y = acc[mi][ni][1] * p.alpha + by;
            v1.x = acc[mi][ni][2] * p.alpha + bx;
            v1.y = acc[mi][ni][3] * p.alpha + by;
            *(float2*)&C[(long)r0 * p.ldc + col]       = v0;
            *(float2*)&C[(long)(r0 + 8) * p.ldc + col] = v1;
        }
    }
}

// ---------------------------------------------------------------------------
// Register-resident talking-heads: pre-mix -> softmax -> post-mix, in-place.
// One CTA (512 thr) per (b,i); thread owns 4 j-cols x 12 heads in registers.
// ---------------------------------------------------------------------------
__global__ void __launch_bounds__(512) mix_softmax2(
    float* __restrict__ dots,
    const float* __restrict__ pre_g,
    const float* __restrict__ post_g)
{
    __shared__ float s_pre[HEADS * HEADS], s_post[HEADS * HEADS];
    __shared__ float red[16][HEADS];
    __shared__ float bm[HEADS], bs[HEADS];

    const int tid = threadIdx.x;
    if (tid < HEADS * HEADS) { s_pre[tid] = pre_g[tid]; s_post[tid] = post_g[tid]; }
    __syncthreads();

    const long base = (long)blockIdx.x * (HEADS * NJ);
    const int j0 = tid * 4;
    const int w = tid >> 5, lane = tid & 31;

    // ---- load + pre-mix (accumulate, one raw head live at a time) ----
    float4 mx[HEADS];
#pragma unroll
    for (int gg = 0; gg < HEADS; gg++) mx[gg] = make_float4(0.f, 0.f, 0.f, 0.f);
#pragma unroll
    for (int h = 0; h < HEADS; h++) {
        float4 r = *(const float4*)(dots + base + (long)h * NJ + j0);
#pragma unroll
        for (int gg = 0; gg < HEADS; gg++) {
            float wv = s_pre[h * HEADS + gg];
            mx[gg].x += r.x * wv;
            mx[gg].y += r.y * wv;
            mx[gg].z += r.z * wv;
            mx[gg].w += r.w * wv;
        }
    }

    // ---- per-head max: local -> warp shfl -> block via smem ----
    float m[HEADS];
#pragma unroll
    for (int gg = 0; gg < HEADS; gg++)
        m[gg] = fmaxf(fmaxf(mx[gg].x, mx[gg].y), fmaxf(mx[gg].z, mx[gg].w));
#pragma unroll
    for (int gg = 0; gg < HEADS; gg++)
#pragma unroll
        for (int o = 16; o; o >>= 1)
            m[gg] = fmaxf(m[gg], __shfl_xor_sync(0xFFFFFFFFu, m[gg], o));
#pragma unroll
    for (int gg = 0; gg < HEADS; gg++)
        if (lane == gg) red[w][gg] = m[gg];
    __syncthreads();
    if (tid < HEADS) {
        float mm = -1e30f;
#pragma unroll
        for (int ww = 0; ww < 16; ww++) mm = fmaxf(mm, red[ww][tid]);
        bm[tid] = mm;
    }
    __syncthreads();

    // ---- exp + per-head sum ----
    float s[HEADS];
#pragma unroll
    for (int gg = 0; gg < HEADS; gg++) {
        float mm = bm[gg];
        mx[gg].x = __expf(mx[gg].x - mm);
        mx[gg].y = __expf(mx[gg].y - mm);
        mx[gg].z = __expf(mx[gg].z - mm);
        mx[gg].w = __expf(mx[gg].w - mm);
        s[gg] = (mx[gg].x + mx[gg].y) + (mx[gg].z + mx[gg].w);
    }
#pragma unroll
    for (int gg = 0; gg < HEADS; gg++)
#pragma unroll
        for (int o = 16; o; o >>= 1)
            s[gg] += __shfl_xor_sync(0xFFFFFFFFu, s[gg], o);
    __syncthreads();   // red round-1 reads complete before reuse
#pragma unroll
    for (int gg = 0; gg < HEADS; gg++)
        if (lane == gg) red[w][gg] = s[gg];
    __syncthreads();
    if (tid < HEADS) {
        float ss = 0.f;
#pragma unroll
        for (int ww = 0; ww < 16; ww++) ss += red[ww][tid];
        bs[tid] = ss;
    }
    __syncthreads();

    // ---- normalize ----
#pragma unroll
    for (int gg = 0; gg < HEADS; gg++) {
        float inv = 1.0f / bs[gg];
        mx[gg].x *= inv; mx[gg].y *= inv; mx[gg].z *= inv; mx[gg].w *= inv;
    }

    // ---- post-mix + writeback ----
#pragma unroll
    for (int gg = 0; gg < HEADS; gg++) {
        float4 o = make_float4(0.f, 0.f, 0.f, 0.f);
#pragma unroll
        for (int h = 0; h < HEADS; h++) {
            float wv = s_post[h * HEADS + gg];
            o.x += mx[h].x * wv;
            o.y += mx[h].y * wv;
            o.z += mx[h].z * wv;
            o.w += mx[h].w * wv;
        }
        *(float4*)(dots + base + (long)gg * NJ + j0) = o;
    }
}

// ---------------------------------------------------------------------------
// Launch
// ---------------------------------------------------------------------------
extern "C" void kernel_launch(void* const* d_in, const int* in_sizes, int n_in,
                              void* d_out, int out_size) {
    (void)in_sizes; (void)n_in; (void)out_size;
    const float* x        = (const float*)d_in[0];
    const float* context  = (const float*)d_in[1];
    const float* Wq       = (const float*)d_in[2];
    const float* Wkv      = (const float*)d_in[3];
    const float* mix_pre  = (const float*)d_in[4];
    const float* mix_post = (const float*)d_in[5];
    const float* Wout     = (const float*)d_in[6];
    const float* b_out    = (const float*)d_in[7];
    float* out = (float*)d_out;

    float *q, *kv, *dots, *ao;
    cudaGetSymbolAddress((void**)&q,    g_q);
    cudaGetSymbolAddress((void**)&kv,   g_kv);
    cudaGetSymbolAddress((void**)&dots, g_dots);
    cudaGetSymbolAddress((void**)&ao,   g_ao);

    const long Q_B  = (long)NQ * INNER;
    const long KV_B = (long)NJ * 2 * INNER;
    const long D_B  = (long)NQ * HEADS * NJ;

    // K1: q = x @ Wq
    {
        GemmParams p = {};
        p.A = x; p.B = Wq; p.C = q;
        p.M = BATCH * NQ; p.N = INNER; p.K = DMODEL;
        p.lda = DMODEL; p.ldb = INNER; p.ldc = INNER;
        p.Z2 = 1; p.alpha = 1.0f;
        mma_gemm<128,128,16,32,64,false,false><<<dim3(INNER/128, BATCH*NQ/128, 1), 256>>>(p);
    }
    // K2: kv = concat(x, context) @ Wkv
    {
        GemmParams p = {};
        p.A = x; p.A2 = context; p.B = Wkv; p.C = kv;
        p.M = NJ; p.N = 2 * INNER; p.K = DMODEL;
        p.lda = DMODEL; p.ldb = 2 * INNER; p.ldc = 2 * INNER;
        p.Z2 = 1; p.as1 = (long)NQ * DMODEL; p.cs1 = KV_B;
        p.alpha = 1.0f; p.gatherSplit = NQ;
        mma_gemm<128,128,16,32,64,false,true><<<dim3(2*INNER/128, NJ/128, BATCH), 256>>>(p);
    }
    // K3: dots = SCALE * q @ k^T   (NT, 48 batch-heads)
    {
        GemmParams p = {};
        p.A = q; p.B = kv; p.C = dots;
        p.M = NQ; p.N = NJ; p.K = DHEAD;
        p.lda = INNER; p.ldb = 2 * INNER; p.ldc = HEADS * NJ;
        p.Z2 = HEADS;
        p.as1 = Q_B;  p.as2 = DHEAD;
        p.bs1 = KV_B; p.bs2 = DHEAD;
        p.cs1 = D_B;  p.cs2 = NJ;
        p.alpha = SCALE;
        mma_gemm<128,128,16,32,64,true,false><<<dim3(NJ/128, NQ/128, BATCH*HEADS), 256>>>(p);
    }
    // K4: fused talking-heads softmax (register-resident)
    mix_softmax2<<<BATCH * NQ, 512>>>(dots, mix_pre, mix_post);
    // K5: ao = attn @ v   (NN, 48 batch-heads)
    {
        GemmParams p = {};
        p.A = dots; p.B = kv + INNER; p.C = ao;
        p.M = NQ; p.N = DHEAD; p.K = NJ;
        p.lda = HEADS * NJ; p.ldb = 2 * INNER; p.ldc = INNER;
        p.Z2 = HEADS;
        p.as1 = D_B;  p.as2 = NJ;
        p.bs1 = KV_B; p.bs2 = DHEAD;
        p.cs1 = Q_B;  p.cs2 = DHEAD;
        p.alpha = 1.0f;
        mma_gemm<128,64,16,32,32,false,false><<<dim3(1, NQ/128, BATCH*HEADS), 256>>>(p);
    }
    // K6: out = ao @ Wout + b_out
    {
        GemmParams p = {};
        p.A = ao; p.B = Wout; p.C = out; p.bias = b_out;
        p.M = BATCH * NQ; p.N = DMODEL; p.K = INNER;
        p.lda = INNER; p.ldb = DMODEL; p.ldc = DMODEL;
        p.Z2 = 1; p.alpha = 1.0f;
        mma_gemm<128,128,16,32,64,false,false><<<dim3(DMODEL/128, BATCH*NQ/128, 1), 256>>>(p);
    }
}